// round 6
// baseline (speedup 1.0000x reference)
#include <cuda_runtime.h>
#include <cuda_fp16.h>
#include <cstdint>

#define NN 100000
#define EE 1600000
#define FIN 128
#define HID 64
#define NCLS 16

#define SCAN_B 512
#define SCAN_NB ((NN + SCAN_B - 1) / SCAN_B)   // 196

// ---- scratch (__device__ globals: allocation-free rule) ----
__device__ __align__(16) int    g_cnt[NN];
__device__ __align__(16) int    g_rowptr[NN + 1];
__device__ __align__(16) int    g_cursor[NN];
__device__ __align__(16) int    g_bsum[SCAN_NB];
__device__ __align__(16) float  g_dinv[NN];
__device__ __align__(16) int2   g_csr[EE];                 // {src, float_bits(w)}
__device__ __align__(16) __half g_h16[(size_t)NN * HID];   // fp16 GEMM output (gathered)
__device__ __align__(16) float  g_x1[(size_t)NN * HID];

static inline int cdiv(long long a, int b) { return (int)((a + b - 1) / b); }

// ---- packed f32x2 helpers (Blackwell FFMA2 via PTX) ----
__device__ __forceinline__ unsigned long long pack2(float lo, float hi) {
    unsigned long long p;
    asm("mov.b64 %0, {%1, %2};" : "=l"(p) : "f"(lo), "f"(hi));
    return p;
}
__device__ __forceinline__ unsigned long long fma2(unsigned long long a,
                                                   unsigned long long b,
                                                   unsigned long long c) {
    unsigned long long d;
    asm("fma.rn.f32x2 %0, %1, %2, %3;" : "=l"(d) : "l"(a), "l"(b), "l"(c));
    return d;
}
__device__ __forceinline__ void unpack2(unsigned long long p, float& lo, float& hi) {
    asm("mov.b64 {%0, %1}, %2;" : "=f"(lo), "=f"(hi) : "l"(p));
}

// ---------------------------------------------------------------------------
// CSR build
// ---------------------------------------------------------------------------
__global__ void k_zero_cnt() {
    int i = blockIdx.x * blockDim.x + threadIdx.x;
    if (i < NN) g_cnt[i] = 0;
}

__global__ void k_hist(const int* __restrict__ ei) {
    int t = blockIdx.x * blockDim.x + threadIdx.x;
    if (t >= EE / 4) return;
    int4 d = *reinterpret_cast<const int4*>(ei + EE + 4 * t);
    atomicAdd(&g_cnt[d.x], 1);
    atomicAdd(&g_cnt[d.y], 1);
    atomicAdd(&g_cnt[d.z], 1);
    atomicAdd(&g_cnt[d.w], 1);
}

// warp-shuffle block scan (exclusive), 512 threads
__global__ void k_scan1() {
    __shared__ int wsum[16];
    int i = blockIdx.x * SCAN_B + threadIdx.x;
    int lane = threadIdx.x & 31;
    int wid = threadIdx.x >> 5;
    int v = (i < NN) ? g_cnt[i] : 0;
    int s = v;
#pragma unroll
    for (int o = 1; o < 32; o <<= 1) {
        int t = __shfl_up_sync(0xffffffffu, s, o);
        if (lane >= o) s += t;
    }
    if (lane == 31) wsum[wid] = s;
    __syncthreads();
    if (wid == 0) {
        int ws = (lane < 16) ? wsum[lane] : 0;
#pragma unroll
        for (int o = 1; o < 16; o <<= 1) {
            int t = __shfl_up_sync(0xffffffffu, ws, o);
            if (lane >= o) ws += t;
        }
        if (lane < 16) wsum[lane] = ws;
    }
    __syncthreads();
    int wpre = (wid > 0) ? wsum[wid - 1] : 0;
    int incl = s + wpre;
    if (i < NN) g_rowptr[i] = incl - v;                 // exclusive
    if (threadIdx.x == SCAN_B - 1) g_bsum[blockIdx.x] = incl;
}

__global__ void k_scan2() {
    __shared__ int wsum[8];
    int t = threadIdx.x;           // 224 threads
    int lane = t & 31;
    int wid = t >> 5;
    int v = (t < SCAN_NB) ? g_bsum[t] : 0;
    int s = v;
#pragma unroll
    for (int o = 1; o < 32; o <<= 1) {
        int u = __shfl_up_sync(0xffffffffu, s, o);
        if (lane >= o) s += u;
    }
    if (lane == 31) wsum[wid] = s;
    __syncthreads();
    if (wid == 0) {
        int ws = (lane < 7) ? wsum[lane] : 0;
#pragma unroll
        for (int o = 1; o < 8; o <<= 1) {
            int u = __shfl_up_sync(0xffffffffu, ws, o);
            if (lane >= o) ws += u;
        }
        if (lane < 7) wsum[lane] = ws;
    }
    __syncthreads();
    int wpre = (wid > 0) ? wsum[wid - 1] : 0;
    if (t < SCAN_NB) g_bsum[t] = s + wpre - v;          // exclusive
}

__global__ void k_scan3() {
    int i = blockIdx.x * blockDim.x + threadIdx.x;
    if (i >= NN) return;
    int rp = g_rowptr[i] + g_bsum[i / SCAN_B];
    g_rowptr[i] = rp;
    g_cursor[i] = rp;
    g_dinv[i] = rsqrtf(1.0f + (float)g_cnt[i]);         // deg + self-loop
    if (i == 0) g_rowptr[NN] = EE;
}

__global__ void k_fill(const int* __restrict__ ei) {
    int e = blockIdx.x * blockDim.x + threadIdx.x;
    if (e >= EE) return;
    int s = ei[e];
    int d = ei[EE + e];
    int pos = atomicAdd(&g_cursor[d], 1);
    g_csr[pos] = make_int2(s, __float_as_int(g_dinv[s] * g_dinv[d]));
}

// ---------------------------------------------------------------------------
// GEMM: g_h16 = fp16(X @ W). One thread per node; packed f32x2 FMA (FFMA2).
// W pre-packed into 64-bit f32 pairs in smem; LDS.128 reads 2 operands.
// ---------------------------------------------------------------------------
template <int K, int O>
__global__ void k_gemm(const float* __restrict__ X, const float* __restrict__ W) {
    __shared__ __align__(16) unsigned long long Ws[K * O / 2];
    for (int i = threadIdx.x; i < K * O / 2; i += blockDim.x) {
        float2 w = reinterpret_cast<const float2*>(W)[i];
        Ws[i] = pack2(w.x, w.y);
    }
    __syncthreads();

    int node = blockIdx.x * blockDim.x + threadIdx.x;
    if (node >= NN) return;

    unsigned long long acc[O / 2];
#pragma unroll
    for (int o = 0; o < O / 2; ++o) acc[o] = 0ull;   // {0.f, 0.f}

    const float4* xr = reinterpret_cast<const float4*>(X + (size_t)node * K);
    for (int k4 = 0; k4 < K / 4; ++k4) {
        float4 xv = xr[k4];
        float xk[4] = {xv.x, xv.y, xv.z, xv.w};
#pragma unroll
        for (int kk = 0; kk < 4; ++kk) {
            unsigned long long xx = pack2(xk[kk], xk[kk]);
            const ulonglong2* wr =
                reinterpret_cast<const ulonglong2*>(&Ws[(k4 * 4 + kk) * (O / 2)]);
#pragma unroll
            for (int o = 0; o < O / 4; ++o) {
                ulonglong2 wp = wr[o];
                acc[2 * o]     = fma2(xx, wp.x, acc[2 * o]);
                acc[2 * o + 1] = fma2(xx, wp.y, acc[2 * o + 1]);
            }
        }
    }

    // unpack, convert to fp16, store vectorized
    __align__(16) __half2 hbuf[O / 2];
#pragma unroll
    for (int o = 0; o < O / 2; ++o) {
        float lo, hi;
        unpack2(acc[o], lo, hi);
        hbuf[o] = __floats2half2_rn(lo, hi);
    }
    uint4* dst = reinterpret_cast<uint4*>(&g_h16[(size_t)node * O]);
    const uint4* srcb = reinterpret_cast<const uint4*>(hbuf);
#pragma unroll
    for (int i = 0; i < (O * 2) / 16; ++i) dst[i] = srcb[i];
}

// ---------------------------------------------------------------------------
// Gather (O=64): 2 nodes per warp, 16 lanes per node. 4-edge batches into 4
// independent accumulators (MLP=4). Invalid tail edges: clamped index + w=0.
// ---------------------------------------------------------------------------
template <bool RELU>
__global__ void k_gather64(const float* __restrict__ b, float* __restrict__ out) {
    int warp = blockIdx.x * (blockDim.x >> 5) + (threadIdx.x >> 5);
    int half = (threadIdx.x >> 4) & 1;
    int node = warp * 2 + half;          // NN even; grid sized exactly
    int lane = threadIdx.x & 15;

    int beg = g_rowptr[node];
    int cnt = g_rowptr[node + 1] - beg;
    int ocnt = __shfl_xor_sync(0xffffffffu, cnt, 16);
    int maxcnt = cnt > ocnt ? cnt : ocnt;
    int cmax = cnt > 0 ? cnt - 1 : 0;

    float4 a0 = make_float4(0.f, 0.f, 0.f, 0.f);
    float4 a1 = a0, a2 = a0, a3 = a0;

    for (int k = 0; k < maxcnt; k += 4) {
        int i0 = beg + min(k,     cmax);
        int i1 = beg + min(k + 1, cmax);
        int i2 = beg + min(k + 2, cmax);
        int i3 = beg + min(k + 3, cmax);
        int2 c0 = __ldg(&g_csr[i0]);
        int2 c1 = __ldg(&g_csr[i1]);
        int2 c2 = __ldg(&g_csr[i2]);
        int2 c3 = __ldg(&g_csr[i3]);
        uint2 u0 = *reinterpret_cast<const uint2*>(&g_h16[(size_t)c0.x * HID + 4 * lane]);
        uint2 u1 = *reinterpret_cast<const uint2*>(&g_h16[(size_t)c1.x * HID + 4 * lane]);
        uint2 u2 = *reinterpret_cast<const uint2*>(&g_h16[(size_t)c2.x * HID + 4 * lane]);
        uint2 u3 = *reinterpret_cast<const uint2*>(&g_h16[(size_t)c3.x * HID + 4 * lane]);
        float w0 = (k     < cnt) ? __int_as_float(c0.y) : 0.f;
        float w1 = (k + 1 < cnt) ? __int_as_float(c1.y) : 0.f;
        float w2 = (k + 2 < cnt) ? __int_as_float(c2.y) : 0.f;
        float w3 = (k + 3 < cnt) ? __int_as_float(c3.y) : 0.f;

        float2 f;
        f = __half22float2(*reinterpret_cast<__half2*>(&u0.x));
        a0.x = fmaf(f.x, w0, a0.x); a0.y = fmaf(f.y, w0, a0.y);
        f = __half22float2(*reinterpret_cast<__half2*>(&u0.y));
        a0.z = fmaf(f.x, w0, a0.z); a0.w = fmaf(f.y, w0, a0.w);

        f = __half22float2(*reinterpret_cast<__half2*>(&u1.x));
        a1.x = fmaf(f.x, w1, a1.x); a1.y = fmaf(f.y, w1, a1.y);
        f = __half22float2(*reinterpret_cast<__half2*>(&u1.y));
        a1.z = fmaf(f.x, w1, a1.z); a1.w = fmaf(f.y, w1, a1.w);

        f = __half22float2(*reinterpret_cast<__half2*>(&u2.x));
        a2.x = fmaf(f.x, w2, a2.x); a2.y = fmaf(f.y, w2, a2.y);
        f = __half22float2(*reinterpret_cast<__half2*>(&u2.y));
        a2.z = fmaf(f.x, w2, a2.z); a2.w = fmaf(f.y, w2, a2.w);

        f = __half22float2(*reinterpret_cast<__half2*>(&u3.x));
        a3.x = fmaf(f.x, w3, a3.x); a3.y = fmaf(f.y, w3, a3.y);
        f = __half22float2(*reinterpret_cast<__half2*>(&u3.y));
        a3.z = fmaf(f.x, w3, a3.z); a3.w = fmaf(f.y, w3, a3.w);
    }

    float4 acc;
    acc.x = (a0.x + a1.x) + (a2.x + a3.x);
    acc.y = (a0.y + a1.y) + (a2.y + a3.y);
    acc.z = (a0.z + a1.z) + (a2.z + a3.z);
    acc.w = (a0.w + a1.w) + (a2.w + a3.w);

    float di = g_dinv[node];
    float s2 = di * di;
    uint2 u = *reinterpret_cast<const uint2*>(&g_h16[(size_t)node * HID + 4 * lane]);
    float2 f01 = __half22float2(*reinterpret_cast<__half2*>(&u.x));
    float2 f23 = __half22float2(*reinterpret_cast<__half2*>(&u.y));
    float4 bv = *reinterpret_cast<const float4*>(&b[4 * lane]);
    acc.x = fmaf(f01.x, s2, acc.x) + bv.x;
    acc.y = fmaf(f01.y, s2, acc.y) + bv.y;
    acc.z = fmaf(f23.x, s2, acc.z) + bv.z;
    acc.w = fmaf(f23.y, s2, acc.w) + bv.w;
    if (RELU) {
        acc.x = fmaxf(acc.x, 0.f);
        acc.y = fmaxf(acc.y, 0.f);
        acc.z = fmaxf(acc.z, 0.f);
        acc.w = fmaxf(acc.w, 0.f);
    }
    *reinterpret_cast<float4*>(&out[(size_t)node * HID + 4 * lane]) = acc;
}

// ---------------------------------------------------------------------------
// Gather (O=16): 2 nodes per warp, 16 lanes x 1 half per node, 4-edge batches.
// ---------------------------------------------------------------------------
template <bool RELU>
__global__ void k_gather16(const float* __restrict__ b, float* __restrict__ out) {
    int warp = blockIdx.x * (blockDim.x >> 5) + (threadIdx.x >> 5);
    int half = (threadIdx.x >> 4) & 1;
    int node = warp * 2 + half;
    int lane = threadIdx.x & 15;

    int beg = g_rowptr[node];
    int cnt = g_rowptr[node + 1] - beg;
    int ocnt = __shfl_xor_sync(0xffffffffu, cnt, 16);
    int maxcnt = cnt > ocnt ? cnt : ocnt;
    int cmax = cnt > 0 ? cnt - 1 : 0;

    float a0 = 0.f, a1 = 0.f, a2 = 0.f, a3 = 0.f;
    for (int k = 0; k < maxcnt; k += 4) {
        int i0 = beg + min(k,     cmax);
        int i1 = beg + min(k + 1, cmax);
        int i2 = beg + min(k + 2, cmax);
        int i3 = beg + min(k + 3, cmax);
        int2 c0 = __ldg(&g_csr[i0]);
        int2 c1 = __ldg(&g_csr[i1]);
        int2 c2 = __ldg(&g_csr[i2]);
        int2 c3 = __ldg(&g_csr[i3]);
        float h0 = __half2float(g_h16[(size_t)c0.x * NCLS + lane]);
        float h1 = __half2float(g_h16[(size_t)c1.x * NCLS + lane]);
        float h2 = __half2float(g_h16[(size_t)c2.x * NCLS + lane]);
        float h3 = __half2float(g_h16[(size_t)c3.x * NCLS + lane]);
        float w0 = (k     < cnt) ? __int_as_float(c0.y) : 0.f;
        float w1 = (k + 1 < cnt) ? __int_as_float(c1.y) : 0.f;
        float w2 = (k + 2 < cnt) ? __int_as_float(c2.y) : 0.f;
        float w3 = (k + 3 < cnt) ? __int_as_float(c3.y) : 0.f;
        a0 = fmaf(h0, w0, a0);
        a1 = fmaf(h1, w1, a1);
        a2 = fmaf(h2, w2, a2);
        a3 = fmaf(h3, w3, a3);
    }
    float acc = (a0 + a1) + (a2 + a3);

    float di = g_dinv[node];
    float hv = __half2float(g_h16[(size_t)node * NCLS + lane]);
    acc = fmaf(hv, di * di, acc) + __ldg(&b[lane]);
    if (RELU) acc = fmaxf(acc, 0.f);
    out[(size_t)node * NCLS + lane] = acc;
}

// ---------------------------------------------------------------------------
// Launch
// ---------------------------------------------------------------------------
extern "C" void kernel_launch(void* const* d_in, const int* in_sizes, int n_in,
                              void* d_out, int out_size) {
    const float* x  = (const float*)d_in[0];
    const int*   ei = (const int*)  d_in[1];
    const float* W1 = (const float*)d_in[2];
    const float* b1 = (const float*)d_in[3];
    const float* Wh = (const float*)d_in[4];
    const float* bh = (const float*)d_in[5];
    const float* W2 = (const float*)d_in[6];
    const float* b2 = (const float*)d_in[7];

    float* logits = (float*)d_out;                       // [N, 16]
    float* latent = (float*)d_out + (size_t)NN * NCLS;   // [N, 64]

    float* x1;
    cudaGetSymbolAddress((void**)&x1, g_x1);

    const int T = 256;
    const int GB = cdiv(NN, 16);   // 2 nodes/warp, 8 warps/block

    // CSR build
    k_zero_cnt<<<cdiv(NN, T), T>>>();
    k_hist<<<cdiv(EE / 4, T), T>>>(ei);
    k_scan1<<<SCAN_NB, SCAN_B>>>();
    k_scan2<<<1, 224>>>();
    k_scan3<<<cdiv(NN, T), T>>>();
    k_fill<<<cdiv(EE, T), T>>>(ei);

    // layer 1: 128 -> 64, relu
    k_gemm<FIN, HID><<<cdiv(NN, 128), 128>>>(x, W1);
    k_gather64<true><<<GB, T>>>(b1, x1);

    // layer 2: 64 -> 64, relu -> latent
    k_gemm<HID, HID><<<cdiv(NN, 128), 128>>>(x1, Wh);
    k_gather64<true><<<GB, T>>>(bh, latent);

    // layer 3: 64 -> 16, logits
    k_gemm<HID, NCLS><<<cdiv(NN, 128), 128>>>(latent, W2);
    k_gather16<false><<<GB, T>>>(b2, logits);
}

// round 7
// speedup vs baseline: 1.0475x; 1.0475x over previous
#include <cuda_runtime.h>
#include <cuda_fp16.h>
#include <cstdint>

#define NN 100000
#define EE 1600000
#define FIN 128
#define HID 64
#define NCLS 16

#define SCAN_B 512
#define SCAN_NB ((NN + SCAN_B - 1) / SCAN_B)   // 196

// ---- scratch (__device__ globals: allocation-free rule) ----
__device__ __align__(16) int    g_cnt[NN];
__device__ __align__(16) int    g_rowptr[NN + 1];
__device__ __align__(16) int    g_cursor[NN];
__device__ __align__(16) int    g_bsum[SCAN_NB];
__device__ __align__(16) float  g_dinv[NN];
__device__ __align__(16) int2   g_csr[EE];                 // {src, float_bits(w)}
__device__ __align__(16) __half g_h16[(size_t)NN * HID];   // fp16 GEMM output (gathered)
__device__ __align__(16) float  g_x1[(size_t)NN * HID];

static inline int cdiv(long long a, int b) { return (int)((a + b - 1) / b); }

// ---------------------------------------------------------------------------
// CSR build
// ---------------------------------------------------------------------------
__global__ void k_zero_cnt() {
    int i = blockIdx.x * blockDim.x + threadIdx.x;
    if (i < NN) g_cnt[i] = 0;
}

__global__ void k_hist(const int* __restrict__ ei) {
    int t = blockIdx.x * blockDim.x + threadIdx.x;
    if (t >= EE / 4) return;
    int4 d = *reinterpret_cast<const int4*>(ei + EE + 4 * t);
    atomicAdd(&g_cnt[d.x], 1);
    atomicAdd(&g_cnt[d.y], 1);
    atomicAdd(&g_cnt[d.z], 1);
    atomicAdd(&g_cnt[d.w], 1);
}

// warp-shuffle block scan (exclusive), 512 threads
__global__ void k_scan1() {
    __shared__ int wsum[16];
    int i = blockIdx.x * SCAN_B + threadIdx.x;
    int lane = threadIdx.x & 31;
    int wid = threadIdx.x >> 5;
    int v = (i < NN) ? g_cnt[i] : 0;
    int s = v;
#pragma unroll
    for (int o = 1; o < 32; o <<= 1) {
        int t = __shfl_up_sync(0xffffffffu, s, o);
        if (lane >= o) s += t;
    }
    if (lane == 31) wsum[wid] = s;
    __syncthreads();
    if (wid == 0) {
        int ws = (lane < 16) ? wsum[lane] : 0;
#pragma unroll
        for (int o = 1; o < 16; o <<= 1) {
            int t = __shfl_up_sync(0xffffffffu, ws, o);
            if (lane >= o) ws += t;
        }
        if (lane < 16) wsum[lane] = ws;
    }
    __syncthreads();
    int wpre = (wid > 0) ? wsum[wid - 1] : 0;
    int incl = s + wpre;
    if (i < NN) g_rowptr[i] = incl - v;                 // exclusive
    if (threadIdx.x == SCAN_B - 1) g_bsum[blockIdx.x] = incl;
}

__global__ void k_scan2() {
    __shared__ int wsum[8];
    int t = threadIdx.x;           // 224 threads
    int lane = t & 31;
    int wid = t >> 5;
    int v = (t < SCAN_NB) ? g_bsum[t] : 0;
    int s = v;
#pragma unroll
    for (int o = 1; o < 32; o <<= 1) {
        int u = __shfl_up_sync(0xffffffffu, s, o);
        if (lane >= o) s += u;
    }
    if (lane == 31) wsum[wid] = s;
    __syncthreads();
    if (wid == 0) {
        int ws = (lane < 7) ? wsum[lane] : 0;
#pragma unroll
        for (int o = 1; o < 8; o <<= 1) {
            int u = __shfl_up_sync(0xffffffffu, ws, o);
            if (lane >= o) ws += u;
        }
        if (lane < 7) wsum[lane] = ws;
    }
    __syncthreads();
    int wpre = (wid > 0) ? wsum[wid - 1] : 0;
    if (t < SCAN_NB) g_bsum[t] = s + wpre - v;          // exclusive
}

__global__ void k_scan3() {
    int i = blockIdx.x * blockDim.x + threadIdx.x;
    if (i >= NN) return;
    int rp = g_rowptr[i] + g_bsum[i / SCAN_B];
    g_rowptr[i] = rp;
    g_cursor[i] = rp;
    g_dinv[i] = rsqrtf(1.0f + (float)g_cnt[i]);         // deg + self-loop
    if (i == 0) g_rowptr[NN] = EE;
}

__global__ void k_fill(const int* __restrict__ ei) {
    int e = blockIdx.x * blockDim.x + threadIdx.x;
    if (e >= EE) return;
    int s = ei[e];
    int d = ei[EE + e];
    int pos = atomicAdd(&g_cursor[d], 1);
    g_csr[pos] = make_int2(s, __float_as_int(g_dinv[s] * g_dinv[d]));
}

// ---------------------------------------------------------------------------
// GEMM: g_h16 = fp16(X @ W). One thread per node; fp32 accumulate. (R5 form)
// ---------------------------------------------------------------------------
template <int K, int O>
__global__ void k_gemm(const float* __restrict__ X, const float* __restrict__ W) {
    __shared__ __align__(16) float Ws[K * O];
    for (int i = threadIdx.x; i < K * O; i += blockDim.x) Ws[i] = W[i];
    __syncthreads();

    int node = blockIdx.x * blockDim.x + threadIdx.x;
    if (node >= NN) return;

    float4 acc[O / 4];
#pragma unroll
    for (int o = 0; o < O / 4; ++o) acc[o] = make_float4(0.f, 0.f, 0.f, 0.f);

    const float4* xr = reinterpret_cast<const float4*>(X + (size_t)node * K);
    for (int k4 = 0; k4 < K / 4; ++k4) {
        float4 xv = xr[k4];
        float xk[4] = {xv.x, xv.y, xv.z, xv.w};
#pragma unroll
        for (int kk = 0; kk < 4; ++kk) {
            const float4* wr = reinterpret_cast<const float4*>(&Ws[(k4 * 4 + kk) * O]);
#pragma unroll
            for (int o = 0; o < O / 4; ++o) {
                float4 w = wr[o];
                acc[o].x = fmaf(xk[kk], w.x, acc[o].x);
                acc[o].y = fmaf(xk[kk], w.y, acc[o].y);
                acc[o].z = fmaf(xk[kk], w.z, acc[o].z);
                acc[o].w = fmaf(xk[kk], w.w, acc[o].w);
            }
        }
    }

    __align__(16) __half2 hbuf[O / 2];
#pragma unroll
    for (int o = 0; o < O / 4; ++o) {
        hbuf[2 * o]     = __floats2half2_rn(acc[o].x, acc[o].y);
        hbuf[2 * o + 1] = __floats2half2_rn(acc[o].z, acc[o].w);
    }
    uint4* dst = reinterpret_cast<uint4*>(&g_h16[(size_t)node * O]);
    const uint4* srcb = reinterpret_cast<const uint4*>(hbuf);
#pragma unroll
    for (int i = 0; i < (O * 2) / 16; ++i) dst[i] = srcb[i];
}

// ---------------------------------------------------------------------------
// Gather (O=64): 2 nodes per warp, 16 lanes per node. 4-edge batches with
// PREDICATED loads (no clamp traffic); w masked to 0 on tail; 4 independent
// accumulators for MLP=4.
// ---------------------------------------------------------------------------
template <bool RELU>
__global__ void k_gather64(const float* __restrict__ b, float* __restrict__ out) {
    int warp = blockIdx.x * (blockDim.x >> 5) + (threadIdx.x >> 5);
    int half = (threadIdx.x >> 4) & 1;
    int node = warp * 2 + half;          // NN even; grid sized exactly
    int lane = threadIdx.x & 15;

    int beg = g_rowptr[node];
    int cnt = g_rowptr[node + 1] - beg;
    int ocnt = __shfl_xor_sync(0xffffffffu, cnt, 16);
    int maxcnt = cnt > ocnt ? cnt : ocnt;

    float4 a0 = make_float4(0.f, 0.f, 0.f, 0.f);
    float4 a1 = a0, a2 = a0, a3 = a0;

    for (int k = 0; k < maxcnt; k += 4) {
        bool p0 = k     < cnt;
        bool p1 = k + 1 < cnt;
        bool p2 = k + 2 < cnt;
        bool p3 = k + 3 < cnt;
        int2 c0 = make_int2(0, 0), c1 = c0, c2 = c0, c3 = c0;
        if (p0) c0 = __ldg(&g_csr[beg + k]);
        if (p1) c1 = __ldg(&g_csr[beg + k + 1]);
        if (p2) c2 = __ldg(&g_csr[beg + k + 2]);
        if (p3) c3 = __ldg(&g_csr[beg + k + 3]);
        uint2 u0 = make_uint2(0u, 0u), u1 = u0, u2 = u0, u3 = u0;
        if (p0) u0 = *reinterpret_cast<const uint2*>(&g_h16[(size_t)c0.x * HID + 4 * lane]);
        if (p1) u1 = *reinterpret_cast<const uint2*>(&g_h16[(size_t)c1.x * HID + 4 * lane]);
        if (p2) u2 = *reinterpret_cast<const uint2*>(&g_h16[(size_t)c2.x * HID + 4 * lane]);
        if (p3) u3 = *reinterpret_cast<const uint2*>(&g_h16[(size_t)c3.x * HID + 4 * lane]);
        float w0 = p0 ? __int_as_float(c0.y) : 0.f;
        float w1 = p1 ? __int_as_float(c1.y) : 0.f;
        float w2 = p2 ? __int_as_float(c2.y) : 0.f;
        float w3 = p3 ? __int_as_float(c3.y) : 0.f;

        float2 f;
        f = __half22float2(*reinterpret_cast<__half2*>(&u0.x));
        a0.x = fmaf(f.x, w0, a0.x); a0.y = fmaf(f.y, w0, a0.y);
        f = __half22float2(*reinterpret_cast<__half2*>(&u0.y));
        a0.z = fmaf(f.x, w0, a0.z); a0.w = fmaf(f.y, w0, a0.w);

        f = __half22float2(*reinterpret_cast<__half2*>(&u1.x));
        a1.x = fmaf(f.x, w1, a1.x); a1.y = fmaf(f.y, w1, a1.y);
        f = __half22float2(*reinterpret_cast<__half2*>(&u1.y));
        a1.z = fmaf(f.x, w1, a1.z); a1.w = fmaf(f.y, w1, a1.w);

        f = __half22float2(*reinterpret_cast<__half2*>(&u2.x));
        a2.x = fmaf(f.x, w2, a2.x); a2.y = fmaf(f.y, w2, a2.y);
        f = __half22float2(*reinterpret_cast<__half2*>(&u2.y));
        a2.z = fmaf(f.x, w2, a2.z); a2.w = fmaf(f.y, w2, a2.w);

        f = __half22float2(*reinterpret_cast<__half2*>(&u3.x));
        a3.x = fmaf(f.x, w3, a3.x); a3.y = fmaf(f.y, w3, a3.y);
        f = __half22float2(*reinterpret_cast<__half2*>(&u3.y));
        a3.z = fmaf(f.x, w3, a3.z); a3.w = fmaf(f.y, w3, a3.w);
    }

    float4 acc;
    acc.x = (a0.x + a1.x) + (a2.x + a3.x);
    acc.y = (a0.y + a1.y) + (a2.y + a3.y);
    acc.z = (a0.z + a1.z) + (a2.z + a3.z);
    acc.w = (a0.w + a1.w) + (a2.w + a3.w);

    float di = g_dinv[node];
    float s2 = di * di;
    uint2 u = *reinterpret_cast<const uint2*>(&g_h16[(size_t)node * HID + 4 * lane]);
    float2 f01 = __half22float2(*reinterpret_cast<__half2*>(&u.x));
    float2 f23 = __half22float2(*reinterpret_cast<__half2*>(&u.y));
    float4 bv = *reinterpret_cast<const float4*>(&b[4 * lane]);
    acc.x = fmaf(f01.x, s2, acc.x) + bv.x;
    acc.y = fmaf(f01.y, s2, acc.y) + bv.y;
    acc.z = fmaf(f23.x, s2, acc.z) + bv.z;
    acc.w = fmaf(f23.y, s2, acc.w) + bv.w;
    if (RELU) {
        acc.x = fmaxf(acc.x, 0.f);
        acc.y = fmaxf(acc.y, 0.f);
        acc.z = fmaxf(acc.z, 0.f);
        acc.w = fmaxf(acc.w, 0.f);
    }
    *reinterpret_cast<float4*>(&out[(size_t)node * HID + 4 * lane]) = acc;
}

// ---------------------------------------------------------------------------
// Gather (O=16): 2 nodes per warp, 16 lanes x 1 half, 4-edge predicated batches.
// ---------------------------------------------------------------------------
template <bool RELU>
__global__ void k_gather16(const float* __restrict__ b, float* __restrict__ out) {
    int warp = blockIdx.x * (blockDim.x >> 5) + (threadIdx.x >> 5);
    int half = (threadIdx.x >> 4) & 1;
    int node = warp * 2 + half;
    int lane = threadIdx.x & 15;

    int beg = g_rowptr[node];
    int cnt = g_rowptr[node + 1] - beg;
    int ocnt = __shfl_xor_sync(0xffffffffu, cnt, 16);
    int maxcnt = cnt > ocnt ? cnt : ocnt;

    float a0 = 0.f, a1 = 0.f, a2 = 0.f, a3 = 0.f;
    for (int k = 0; k < maxcnt; k += 4) {
        bool p0 = k     < cnt;
        bool p1 = k + 1 < cnt;
        bool p2 = k + 2 < cnt;
        bool p3 = k + 3 < cnt;
        int2 c0 = make_int2(0, 0), c1 = c0, c2 = c0, c3 = c0;
        if (p0) c0 = __ldg(&g_csr[beg + k]);
        if (p1) c1 = __ldg(&g_csr[beg + k + 1]);
        if (p2) c2 = __ldg(&g_csr[beg + k + 2]);
        if (p3) c3 = __ldg(&g_csr[beg + k + 3]);
        float h0 = 0.f, h1 = 0.f, h2 = 0.f, h3 = 0.f;
        if (p0) h0 = __half2float(g_h16[(size_t)c0.x * NCLS + lane]);
        if (p1) h1 = __half2float(g_h16[(size_t)c1.x * NCLS + lane]);
        if (p2) h2 = __half2float(g_h16[(size_t)c2.x * NCLS + lane]);
        if (p3) h3 = __half2float(g_h16[(size_t)c3.x * NCLS + lane]);
        float w0 = p0 ? __int_as_float(c0.y) : 0.f;
        float w1 = p1 ? __int_as_float(c1.y) : 0.f;
        float w2 = p2 ? __int_as_float(c2.y) : 0.f;
        float w3 = p3 ? __int_as_float(c3.y) : 0.f;
        a0 = fmaf(h0, w0, a0);
        a1 = fmaf(h1, w1, a1);
        a2 = fmaf(h2, w2, a2);
        a3 = fmaf(h3, w3, a3);
    }
    float acc = (a0 + a1) + (a2 + a3);

    float di = g_dinv[node];
    float hv = __half2float(g_h16[(size_t)node * NCLS + lane]);
    acc = fmaf(hv, di * di, acc) + __ldg(&b[lane]);
    if (RELU) acc = fmaxf(acc, 0.f);
    out[(size_t)node * NCLS + lane] = acc;
}

// ---------------------------------------------------------------------------
// Launch
// ---------------------------------------------------------------------------
extern "C" void kernel_launch(void* const* d_in, const int* in_sizes, int n_in,
                              void* d_out, int out_size) {
    const float* x  = (const float*)d_in[0];
    const int*   ei = (const int*)  d_in[1];
    const float* W1 = (const float*)d_in[2];
    const float* b1 = (const float*)d_in[3];
    const float* Wh = (const float*)d_in[4];
    const float* bh = (const float*)d_in[5];
    const float* W2 = (const float*)d_in[6];
    const float* b2 = (const float*)d_in[7];

    float* logits = (float*)d_out;                       // [N, 16]
    float* latent = (float*)d_out + (size_t)NN * NCLS;   // [N, 64]

    float* x1;
    cudaGetSymbolAddress((void**)&x1, g_x1);

    const int T = 256;
    const int GB = cdiv(NN, 16);   // 2 nodes/warp, 8 warps/block

    // CSR build
    k_zero_cnt<<<cdiv(NN, T), T>>>();
    k_hist<<<cdiv(EE / 4, T), T>>>(ei);
    k_scan1<<<SCAN_NB, SCAN_B>>>();
    k_scan2<<<1, 224>>>();
    k_scan3<<<cdiv(NN, T), T>>>();
    k_fill<<<cdiv(EE, T), T>>>(ei);

    // layer 1: 128 -> 64, relu
    k_gemm<FIN, HID><<<cdiv(NN, 128), 128>>>(x, W1);
    k_gather64<true><<<GB, T>>>(b1, x1);

    // layer 2: 64 -> 64, relu -> latent
    k_gemm<HID, HID><<<cdiv(NN, 128), 128>>>(x1, Wh);
    k_gather64<true><<<GB, T>>>(bh, latent);

    // layer 3: 64 -> 16, logits
    k_gemm<HID, NCLS><<<cdiv(NN, 128), 128>>>(latent, W2);
    k_gather16<false><<<GB, T>>>(b2, logits);
}

// round 8
// speedup vs baseline: 1.1570x; 1.1045x over previous
#include <cuda_runtime.h>
#include <cuda_fp16.h>
#include <cstdint>

#define NN 100000
#define EE 1600000
#define FIN 128
#define HID 64
#define NCLS 16

#define SCAN_B 512
#define SCAN_NB ((NN + SCAN_B - 1) / SCAN_B)   // 196

// ---- scratch (__device__ globals: allocation-free rule) ----
__device__ __align__(16) int    g_cnt[NN];
__device__ __align__(16) int    g_rowptr[NN + 1];
__device__ __align__(16) int    g_cursor[NN];
__device__ __align__(16) int    g_bsum[SCAN_NB];
__device__ __align__(16) float  g_dinv[NN];
__device__ __align__(16) int2   g_csr[EE];                 // {src, float_bits(w)}
__device__ __align__(16) __half g_h16[(size_t)NN * HID];   // fp16 GEMM output (gathered)
__device__ __align__(16) float  g_x1[(size_t)NN * HID];

static inline int cdiv(long long a, int b) { return (int)((a + b - 1) / b); }

// ---- side stream + events for capture fork/join (created at static init,
// no device memory involved) ----
struct HxAsync {
    cudaStream_t s1;
    cudaEvent_t e_fork, e_join;
    HxAsync() {
        cudaStreamCreateWithFlags(&s1, cudaStreamNonBlocking);
        cudaEventCreateWithFlags(&e_fork, cudaEventDisableTiming);
        cudaEventCreateWithFlags(&e_join, cudaEventDisableTiming);
    }
};
static HxAsync g_hx;

// ---------------------------------------------------------------------------
// CSR build
// ---------------------------------------------------------------------------
__global__ void k_zero_cnt() {
    int i = blockIdx.x * blockDim.x + threadIdx.x;
    if (i < NN) g_cnt[i] = 0;
}

__global__ void k_hist(const int* __restrict__ ei) {
    int t = blockIdx.x * blockDim.x + threadIdx.x;
    if (t >= EE / 4) return;
    int4 d = *reinterpret_cast<const int4*>(ei + EE + 4 * t);
    atomicAdd(&g_cnt[d.x], 1);
    atomicAdd(&g_cnt[d.y], 1);
    atomicAdd(&g_cnt[d.z], 1);
    atomicAdd(&g_cnt[d.w], 1);
}

// warp-shuffle block scan (exclusive), 512 threads
__global__ void k_scan1() {
    __shared__ int wsum[16];
    int i = blockIdx.x * SCAN_B + threadIdx.x;
    int lane = threadIdx.x & 31;
    int wid = threadIdx.x >> 5;
    int v = (i < NN) ? g_cnt[i] : 0;
    int s = v;
#pragma unroll
    for (int o = 1; o < 32; o <<= 1) {
        int t = __shfl_up_sync(0xffffffffu, s, o);
        if (lane >= o) s += t;
    }
    if (lane == 31) wsum[wid] = s;
    __syncthreads();
    if (wid == 0) {
        int ws = (lane < 16) ? wsum[lane] : 0;
#pragma unroll
        for (int o = 1; o < 16; o <<= 1) {
            int t = __shfl_up_sync(0xffffffffu, ws, o);
            if (lane >= o) ws += t;
        }
        if (lane < 16) wsum[lane] = ws;
    }
    __syncthreads();
    int wpre = (wid > 0) ? wsum[wid - 1] : 0;
    int incl = s + wpre;
    if (i < NN) g_rowptr[i] = incl - v;                 // exclusive
    if (threadIdx.x == SCAN_B - 1) g_bsum[blockIdx.x] = incl;
}

__global__ void k_scan2() {
    __shared__ int wsum[8];
    int t = threadIdx.x;           // 224 threads
    int lane = t & 31;
    int wid = t >> 5;
    int v = (t < SCAN_NB) ? g_bsum[t] : 0;
    int s = v;
#pragma unroll
    for (int o = 1; o < 32; o <<= 1) {
        int u = __shfl_up_sync(0xffffffffu, s, o);
        if (lane >= o) s += u;
    }
    if (lane == 31) wsum[wid] = s;
    __syncthreads();
    if (wid == 0) {
        int ws = (lane < 7) ? wsum[lane] : 0;
#pragma unroll
        for (int o = 1; o < 8; o <<= 1) {
            int u = __shfl_up_sync(0xffffffffu, ws, o);
            if (lane >= o) ws += u;
        }
        if (lane < 7) wsum[lane] = ws;
    }
    __syncthreads();
    int wpre = (wid > 0) ? wsum[wid - 1] : 0;
    if (t < SCAN_NB) g_bsum[t] = s + wpre - v;          // exclusive
}

__global__ void k_scan3() {
    int i = blockIdx.x * blockDim.x + threadIdx.x;
    if (i >= NN) return;
    int rp = g_rowptr[i] + g_bsum[i / SCAN_B];
    g_rowptr[i] = rp;
    g_cursor[i] = rp;
    g_dinv[i] = rsqrtf(1.0f + (float)g_cnt[i]);         // deg + self-loop
    if (i == 0) g_rowptr[NN] = EE;
}

__global__ void k_fill(const int* __restrict__ ei) {
    int e = blockIdx.x * blockDim.x + threadIdx.x;
    if (e >= EE) return;
    int s = ei[e];
    int d = ei[EE + e];
    int pos = atomicAdd(&g_cursor[d], 1);
    g_csr[pos] = make_int2(s, __float_as_int(g_dinv[s] * g_dinv[d]));
}

// ---------------------------------------------------------------------------
// GEMM: g_h16 = fp16(X @ W). One thread per node; fp32 accumulate. (R5 form)
// ---------------------------------------------------------------------------
template <int K, int O>
__global__ void k_gemm(const float* __restrict__ X, const float* __restrict__ W) {
    __shared__ __align__(16) float Ws[K * O];
    for (int i = threadIdx.x; i < K * O; i += blockDim.x) Ws[i] = W[i];
    __syncthreads();

    int node = blockIdx.x * blockDim.x + threadIdx.x;
    if (node >= NN) return;

    float4 acc[O / 4];
#pragma unroll
    for (int o = 0; o < O / 4; ++o) acc[o] = make_float4(0.f, 0.f, 0.f, 0.f);

    const float4* xr = reinterpret_cast<const float4*>(X + (size_t)node * K);
    for (int k4 = 0; k4 < K / 4; ++k4) {
        float4 xv = xr[k4];
        float xk[4] = {xv.x, xv.y, xv.z, xv.w};
#pragma unroll
        for (int kk = 0; kk < 4; ++kk) {
            const float4* wr = reinterpret_cast<const float4*>(&Ws[(k4 * 4 + kk) * O]);
#pragma unroll
            for (int o = 0; o < O / 4; ++o) {
                float4 w = wr[o];
                acc[o].x = fmaf(xk[kk], w.x, acc[o].x);
                acc[o].y = fmaf(xk[kk], w.y, acc[o].y);
                acc[o].z = fmaf(xk[kk], w.z, acc[o].z);
                acc[o].w = fmaf(xk[kk], w.w, acc[o].w);
            }
        }
    }

    __align__(16) __half2 hbuf[O / 2];
#pragma unroll
    for (int o = 0; o < O / 4; ++o) {
        hbuf[2 * o]     = __floats2half2_rn(acc[o].x, acc[o].y);
        hbuf[2 * o + 1] = __floats2half2_rn(acc[o].z, acc[o].w);
    }
    uint4* dst = reinterpret_cast<uint4*>(&g_h16[(size_t)node * O]);
    const uint4* srcb = reinterpret_cast<const uint4*>(hbuf);
#pragma unroll
    for (int i = 0; i < (O * 2) / 16; ++i) dst[i] = srcb[i];
}

// ---------------------------------------------------------------------------
// Gather (O=64): 2 nodes per warp, 16 lanes x 4 halves (uint2 load) per node.
// Joint max-deg loop (predicated); uniform int2 CSR loads. fp32 accumulate.
// (R5 form — validated optimum)
// ---------------------------------------------------------------------------
template <bool RELU>
__global__ void k_gather64(const float* __restrict__ b, float* __restrict__ out) {
    int warp = blockIdx.x * (blockDim.x >> 5) + (threadIdx.x >> 5);
    int half = (threadIdx.x >> 4) & 1;
    int node = warp * 2 + half;          // NN even; grid sized exactly
    int lane = threadIdx.x & 15;

    int beg = g_rowptr[node];
    int cnt = g_rowptr[node + 1] - beg;
    int ocnt = __shfl_xor_sync(0xffffffffu, cnt, 16);
    int maxcnt = cnt > ocnt ? cnt : ocnt;

    float4 acc = make_float4(0.f, 0.f, 0.f, 0.f);
#pragma unroll 2
    for (int k = 0; k < maxcnt; ++k) {
        if (k < cnt) {
            int2 c = __ldg(&g_csr[beg + k]);
            float w = __int_as_float(c.y);
            uint2 u = *reinterpret_cast<const uint2*>(&g_h16[(size_t)c.x * HID + 4 * lane]);
            float2 f01 = __half22float2(*reinterpret_cast<__half2*>(&u.x));
            float2 f23 = __half22float2(*reinterpret_cast<__half2*>(&u.y));
            acc.x = fmaf(f01.x, w, acc.x);
            acc.y = fmaf(f01.y, w, acc.y);
            acc.z = fmaf(f23.x, w, acc.z);
            acc.w = fmaf(f23.y, w, acc.w);
        }
    }

    float di = g_dinv[node];
    float s2 = di * di;
    uint2 u = *reinterpret_cast<const uint2*>(&g_h16[(size_t)node * HID + 4 * lane]);
    float2 f01 = __half22float2(*reinterpret_cast<__half2*>(&u.x));
    float2 f23 = __half22float2(*reinterpret_cast<__half2*>(&u.y));
    float4 bv = *reinterpret_cast<const float4*>(&b[4 * lane]);
    acc.x = fmaf(f01.x, s2, acc.x) + bv.x;
    acc.y = fmaf(f01.y, s2, acc.y) + bv.y;
    acc.z = fmaf(f23.x, s2, acc.z) + bv.z;
    acc.w = fmaf(f23.y, s2, acc.w) + bv.w;
    if (RELU) {
        acc.x = fmaxf(acc.x, 0.f);
        acc.y = fmaxf(acc.y, 0.f);
        acc.z = fmaxf(acc.z, 0.f);
        acc.w = fmaxf(acc.w, 0.f);
    }
    *reinterpret_cast<float4*>(&out[(size_t)node * HID + 4 * lane]) = acc;
}

// ---------------------------------------------------------------------------
// Gather (O=16): 2 nodes per warp, 16 lanes x 1 half per node. (R5 form)
// ---------------------------------------------------------------------------
template <bool RELU>
__global__ void k_gather16(const float* __restrict__ b, float* __restrict__ out) {
    int warp = blockIdx.x * (blockDim.x >> 5) + (threadIdx.x >> 5);
    int half = (threadIdx.x >> 4) & 1;
    int node = warp * 2 + half;
    int lane = threadIdx.x & 15;

    int beg = g_rowptr[node];
    int cnt = g_rowptr[node + 1] - beg;
    int ocnt = __shfl_xor_sync(0xffffffffu, cnt, 16);
    int maxcnt = cnt > ocnt ? cnt : ocnt;

    float acc = 0.f;
#pragma unroll 2
    for (int k = 0; k < maxcnt; ++k) {
        if (k < cnt) {
            int2 c = __ldg(&g_csr[beg + k]);
            float w = __int_as_float(c.y);
            float hv = __half2float(g_h16[(size_t)c.x * NCLS + lane]);
            acc = fmaf(hv, w, acc);
        }
    }

    float di = g_dinv[node];
    float hv = __half2float(g_h16[(size_t)node * NCLS + lane]);
    acc = fmaf(hv, di * di, acc) + __ldg(&b[lane]);
    if (RELU) acc = fmaxf(acc, 0.f);
    out[(size_t)node * NCLS + lane] = acc;
}

// ---------------------------------------------------------------------------
// Launch: CSR build on default stream, layer-1 GEMM concurrently on side
// stream (capture fork/join via events); join before the first gather.
// ---------------------------------------------------------------------------
extern "C" void kernel_launch(void* const* d_in, const int* in_sizes, int n_in,
                              void* d_out, int out_size) {
    const float* x  = (const float*)d_in[0];
    const int*   ei = (const int*)  d_in[1];
    const float* W1 = (const float*)d_in[2];
    const float* b1 = (const float*)d_in[3];
    const float* Wh = (const float*)d_in[4];
    const float* bh = (const float*)d_in[5];
    const float* W2 = (const float*)d_in[6];
    const float* b2 = (const float*)d_in[7];

    float* logits = (float*)d_out;                       // [N, 16]
    float* latent = (float*)d_out + (size_t)NN * NCLS;   // [N, 64]

    float* x1;
    cudaGetSymbolAddress((void**)&x1, g_x1);

    const int T = 256;
    const int GB = cdiv(NN, 16);   // 2 nodes/warp, 8 warps/block

    // ---- fork: layer-1 GEMM on side stream (independent of CSR build) ----
    cudaEventRecord(g_hx.e_fork, 0);
    cudaStreamWaitEvent(g_hx.s1, g_hx.e_fork, 0);
    k_gemm<FIN, HID><<<cdiv(NN, 128), 128, 0, g_hx.s1>>>(x, W1);
    cudaEventRecord(g_hx.e_join, g_hx.s1);

    // ---- CSR build on default stream (concurrent with GEMM1) ----
    k_zero_cnt<<<cdiv(NN, T), T>>>();
    k_hist<<<cdiv(EE / 4, T), T>>>(ei);
    k_scan1<<<SCAN_NB, SCAN_B>>>();
    k_scan2<<<1, 224>>>();
    k_scan3<<<cdiv(NN, T), T>>>();
    k_fill<<<cdiv(EE, T), T>>>(ei);

    // ---- join: first gather needs both CSR and g_h16 ----
    cudaStreamWaitEvent(0, g_hx.e_join, 0);

    // layer 1: 128 -> 64, relu
    k_gather64<true><<<GB, T>>>(b1, x1);

    // layer 2: 64 -> 64, relu -> latent
    k_gemm<HID, HID><<<cdiv(NN, 128), 128>>>(x1, Wh);
    k_gather64<true><<<GB, T>>>(bh, latent);

    // layer 3: 64 -> 16, logits
    k_gemm<HID, NCLS><<<cdiv(NN, 128), 128>>>(latent, W2);
    k_gather16<false><<<GB, T>>>(b2, logits);
}